// round 2
// baseline (speedup 1.0000x reference)
#include <cuda_runtime.h>
#include <stdint.h>

// ---------------------------------------------------------------------------
// VanDerWallsSurface: scatter point features into a 128^3 voxel grid.
//  out[b,x,y,z] = [max f0, min f1, mean f2] over points whose sphere covers
//  the voxel (within the 5x5x5 neighborhood of round(coords)), else zeros.
//
// R2: removed the single-address g_counter atomic (it serialized at ~0.854
// cyc/op -> ~195us, the R1 bottleneck). Finalize now scans g_cnt directly
// (33.5MB vectorized read ~5us) instead of a compacted touch-list. All
// remaining atomics are address-spread.
//
//  - Order-preserving uint encodings make 0 the neutral element for all four
//    accumulators (max-key, ~min-key, sum, count) -> scratch arrays are
//    zero-initialized statics and re-zeroed lazily (touched entries only) by
//    the finalize kernel, keeping the all-zero invariant across graph replays.
//  - Kernel A fuses the mandatory 100MB output zeroing with the atomic
//    scatter; the two halves of the grid touch disjoint memory.
//  - Kernel B scans cnt, finalizes touched voxels, self-cleans scratch.
// ---------------------------------------------------------------------------

#define VOL        128
#define NB         4
#define NPTS       4096
#define NPOINTS    (NB * NPTS)            // 16384
#define KOFF       125                    // 5x5x5 offsets
#define NCAND      (NPOINTS * KOFF)       // 2,048,000 candidates
#define TOTAL_VOX  (NB * VOL * VOL * VOL) // 8,388,608
#define TPB        256

#define ZPT         4                                   // float4 stores per thread
#define ZERO_VEC    ((TOTAL_VOX * 3) / 4)               // 6,291,456 float4 stores
#define ZERO_BLOCKS (ZERO_VEC / (TPB * ZPT))            // 6,144
#define SCAT_BLOCKS (NCAND / TPB)                       // 8,000
#define FIN_BLOCKS  ((TOTAL_VOX / 4) / TPB)             // 8,192

// Scratch (zero-initialized at module load; kept zero by k_finalize).
__device__ unsigned int g_maxk[TOTAL_VOX];   // max-key of f0, neutral = 0
__device__ unsigned int g_mink[TOTAL_VOX];   // ~min-key of f1 (max form), neutral = 0
__device__ float        g_sum [TOTAL_VOX];   // sum f2, neutral = 0
__device__ unsigned int g_cnt [TOTAL_VOX];   // count, neutral = 0

// Order-preserving float -> uint key. For any finite non-NaN f, fkey(f) > 0,
// so 0 is a valid "empty" sentinel for atomicMax accumulation.
__device__ __forceinline__ unsigned int fkey(float f) {
    unsigned int u = __float_as_uint(f);
    return (u & 0x80000000u) ? ~u : (u | 0x80000000u);
}
__device__ __forceinline__ float funkey(unsigned int k) {
    unsigned int u = (k & 0x80000000u) ? (k ^ 0x80000000u) : ~k;
    return __uint_as_float(u);
}

// Kernel A: blocks [0, ZERO_BLOCKS) zero d_out (64B/thread); blocks
// [ZERO_BLOCKS, ...) run the scatter. The two halves touch disjoint memory.
__global__ void __launch_bounds__(TPB) k_zero_scatter(
    const float4* __restrict__ cr,     // (B*N) x [cx, cy, cz, r]
    const float*  __restrict__ feat,   // (B*N) x 3
    float4*       __restrict__ out4)   // d_out viewed as float4
{
    int bid = blockIdx.x;
    if (bid < ZERO_BLOCKS) {
        size_t base = ((size_t)bid * TPB + threadIdx.x) * ZPT;
        float4 z = make_float4(0.f, 0.f, 0.f, 0.f);
#pragma unroll
        for (int j = 0; j < ZPT; j++) out4[base + j] = z;
        return;
    }

    int t  = (bid - ZERO_BLOCKS) * TPB + threadIdx.x;  // candidate id
    int k  = t % KOFF;
    int pn = t / KOFF;                                  // linear point id

    float4 c = __ldg(cr + pn);  // 125 consecutive threads share -> L1 broadcast

    int ox = k / 25 - 2;
    int oy = (k / 5) % 5 - 2;
    int oz = k % 5 - 2;

    // jnp.round == round-half-to-even == rn conversions/rintf
    int vx = __float2int_rn(c.x) + ox;
    int vy = __float2int_rn(c.y) + oy;
    int vz = __float2int_rn(c.z) + oz;

    // Exact IEEE ops, left-to-right sum, matching the reference (no FMA
    // contraction that could flip sphere-boundary membership).
    float dx = __fsub_rn((float)vx, c.x);
    float dy = __fsub_rn((float)vy, c.y);
    float dz = __fsub_rn((float)vz, c.z);
    float d2 = __fadd_rn(__fadd_rn(__fmul_rn(dx, dx), __fmul_rn(dy, dy)),
                         __fmul_rn(dz, dz));

    float rr = __fdiv_rn(rintf(__fmul_rn(c.w, 1000.0f)), 1000.0f);
    float r2 = __fmul_rn(rr, rr);

    bool ok = (d2 <= r2)
            && ((unsigned)vx < VOL) && ((unsigned)vy < VOL) && ((unsigned)vz < VOL);
    if (!ok) return;

    unsigned e = (unsigned)((pn >> 12) * (VOL * VOL * VOL)
                            + ((vx * VOL + vy) * VOL + vz));

    const float* fp = feat + (size_t)pn * 3;
    float f0 = __ldg(fp + 0);
    float f1 = __ldg(fp + 1);
    float f2 = __ldg(fp + 2);

    atomicMax(&g_maxk[e], fkey(f0));
    atomicMax(&g_mink[e], ~fkey(f1));   // min via max of complemented key
    atomicAdd(&g_sum[e], f2);
    atomicAdd(&g_cnt[e], 1u);
}

// Kernel B: scan cnt (uint4-vectorized), finalize touched voxels, and restore
// scratch to all-zero. Untouched groups cost one 16B read, no writes.
__global__ void __launch_bounds__(TPB) k_finalize(float* __restrict__ out)
{
    unsigned g = blockIdx.x * TPB + threadIdx.x;      // group of 4 voxels
    uint4 c4 = *reinterpret_cast<const uint4*>(&g_cnt[g * 4]);
    if ((c4.x | c4.y | c4.z | c4.w) == 0u) return;

    unsigned cs[4] = {c4.x, c4.y, c4.z, c4.w};
#pragma unroll
    for (int j = 0; j < 4; j++) {
        if (cs[j] == 0u) continue;
        unsigned e  = g * 4 + j;
        unsigned mk = g_maxk[e];
        unsigned nk = g_mink[e];
        float    s  = g_sum[e];
        g_maxk[e] = 0u;                     // self-clean for next call
        g_mink[e] = 0u;
        g_sum[e]  = 0.0f;

        size_t o = (size_t)e * 3;
        out[o + 0] = funkey(mk);
        out[o + 1] = funkey(~nk);
        out[o + 2] = __fdiv_rn(s, (float)cs[j]);  // cnt >= 1 (== max(cnt,1))
    }
    *reinterpret_cast<uint4*>(&g_cnt[g * 4]) = make_uint4(0u, 0u, 0u, 0u);
}

extern "C" void kernel_launch(void* const* d_in, const int* in_sizes, int n_in,
                              void* d_out, int out_size)
{
    const float4* cr   = (const float4*)d_in[0];  // coordinates_radii (B,N,4)
    const float*  feat = (const float*)d_in[1];   // features (B,N,3)
    float*        out  = (float*)d_out;           // (B,128,128,128,3) f32

    k_zero_scatter<<<ZERO_BLOCKS + SCAT_BLOCKS, TPB>>>(cr, feat, (float4*)out);
    k_finalize<<<FIN_BLOCKS, TPB>>>(out);
}

// round 3
// speedup vs baseline: 1.4171x; 1.4171x over previous
#include <cuda_runtime.h>
#include <stdint.h>

// ---------------------------------------------------------------------------
// VanDerWallsSurface: scatter point features into a 128^3 voxel grid.
//  out[b,x,y,z] = [max f0, min f1, mean f2] over points whose sphere covers
//  the voxel (within the 5x5x5 neighborhood of round(coords)), else zeros.
//
// R3: evidence-driven redesign of the touch tracking.
//  R1: single-address g_counter atomic serialized (~0.854cyc/op x 330k) ->
//      scatter kernel 167us. Its list-driven finalize was cheap (~30us).
//  R2: full g_cnt scan finalize exploded to 325us (420MB of scattered L2
//      traffic, latency-bound at issue=1.7%).
//  R3: compact list WITHOUT atomics: scatter thread t owns list slot t and
//      writes voxel-id or sentinel (coalesced 8MB store); finalize does a
//      coalesced 8MB read and only touches hit entries (L2-hot scratch).
//
//  - Order-preserving uint encodings make 0 the neutral element for all four
//    accumulators (max-key, ~min-key, sum, count) -> scratch arrays are
//    zero-initialized statics and re-zeroed lazily (touched entries only) by
//    the finalize kernel, keeping the all-zero invariant across graph replays.
//  - Kernel A fuses the mandatory 100MB output zeroing with the atomic
//    scatter; the two halves of the grid touch disjoint memory.
//  - Kernel B walks the candidate list, claims each touched voxel once via
//    atomicExch on cnt, writes its 3 output channels, zeroes its scratch.
// ---------------------------------------------------------------------------

#define VOL        128
#define NB         4
#define NPTS       4096
#define NPOINTS    (NB * NPTS)            // 16384
#define KOFF       125                    // 5x5x5 offsets
#define NCAND      (NPOINTS * KOFF)       // 2,048,000 candidates
#define TOTAL_VOX  (NB * VOL * VOL * VOL) // 8,388,608
#define TPB        256
#define SENTINEL   0xFFFFFFFFu

#define ZPT         4                                   // float4 stores per thread
#define ZERO_VEC    ((TOTAL_VOX * 3) / 4)               // 6,291,456 float4 stores
#define ZERO_BLOCKS (ZERO_VEC / (TPB * ZPT))            // 6,144
#define SCAT_BLOCKS (NCAND / TPB)                       // 8,000
#define FIN_BLOCKS  (NCAND / TPB)                       // 8,000

// Scratch (zero-initialized at module load; kept zero by k_finalize).
__device__ unsigned int g_maxk[TOTAL_VOX];   // max-key of f0, neutral = 0
__device__ unsigned int g_mink[TOTAL_VOX];   // ~min-key of f1 (max form), neutral = 0
__device__ float        g_sum [TOTAL_VOX];   // sum f2, neutral = 0
__device__ unsigned int g_cnt [TOTAL_VOX];   // count, neutral = 0
__device__ unsigned int g_list[NCAND];       // per-candidate voxel id / SENTINEL
                                             // (fully rewritten every call)

// Order-preserving float -> uint key. For any finite non-NaN f, fkey(f) > 0,
// so 0 is a valid "empty" sentinel for atomicMax accumulation.
__device__ __forceinline__ unsigned int fkey(float f) {
    unsigned int u = __float_as_uint(f);
    return (u & 0x80000000u) ? ~u : (u | 0x80000000u);
}
__device__ __forceinline__ float funkey(unsigned int k) {
    unsigned int u = (k & 0x80000000u) ? (k ^ 0x80000000u) : ~k;
    return __uint_as_float(u);
}

// Kernel A: blocks [0, ZERO_BLOCKS) zero d_out (64B/thread); blocks
// [ZERO_BLOCKS, ...) run the scatter. The two halves touch disjoint memory.
__global__ void __launch_bounds__(TPB) k_zero_scatter(
    const float4* __restrict__ cr,     // (B*N) x [cx, cy, cz, r]
    const float*  __restrict__ feat,   // (B*N) x 3
    float4*       __restrict__ out4)   // d_out viewed as float4
{
    int bid = blockIdx.x;
    if (bid < ZERO_BLOCKS) {
        size_t base = ((size_t)bid * TPB + threadIdx.x) * ZPT;
        float4 z = make_float4(0.f, 0.f, 0.f, 0.f);
#pragma unroll
        for (int j = 0; j < ZPT; j++) out4[base + j] = z;
        return;
    }

    int t  = (bid - ZERO_BLOCKS) * TPB + threadIdx.x;  // candidate id
    int k  = t % KOFF;
    int pn = t / KOFF;                                  // linear point id

    float4 c = __ldg(cr + pn);  // 125 consecutive threads share -> L1 broadcast

    int ox = k / 25 - 2;
    int oy = (k / 5) % 5 - 2;
    int oz = k % 5 - 2;

    // jnp.round == round-half-to-even == rn conversions/rintf
    int vx = __float2int_rn(c.x) + ox;
    int vy = __float2int_rn(c.y) + oy;
    int vz = __float2int_rn(c.z) + oz;

    // Exact IEEE ops, left-to-right sum, matching the reference (no FMA
    // contraction that could flip sphere-boundary membership).
    float dx = __fsub_rn((float)vx, c.x);
    float dy = __fsub_rn((float)vy, c.y);
    float dz = __fsub_rn((float)vz, c.z);
    float d2 = __fadd_rn(__fadd_rn(__fmul_rn(dx, dx), __fmul_rn(dy, dy)),
                         __fmul_rn(dz, dz));

    float rr = __fdiv_rn(rintf(__fmul_rn(c.w, 1000.0f)), 1000.0f);
    float r2 = __fmul_rn(rr, rr);

    bool ok = (d2 <= r2)
            && ((unsigned)vx < VOL) && ((unsigned)vy < VOL) && ((unsigned)vz < VOL);

    unsigned e = (unsigned)((pn >> 12) * (VOL * VOL * VOL)
                            + ((vx * VOL + vy) * VOL + vz));

    g_list[t] = ok ? e : SENTINEL;      // coalesced, no atomics, every slot
    if (!ok) return;

    const float* fp = feat + (size_t)pn * 3;
    float f0 = __ldg(fp + 0);
    float f1 = __ldg(fp + 1);
    float f2 = __ldg(fp + 2);

    atomicMax(&g_maxk[e], fkey(f0));
    atomicMax(&g_mink[e], ~fkey(f1));   // min via max of complemented key
    atomicAdd(&g_sum[e], f2);
    atomicAdd(&g_cnt[e], 1u);
}

// Kernel B: walk the candidate list (coalesced 8MB read); for each hit, claim
// the voxel once (atomicExch on cnt), finalize its 3 channels, and restore
// its scratch entries to zero for the next call.
__global__ void __launch_bounds__(TPB) k_finalize(float* __restrict__ out)
{
    unsigned i = blockIdx.x * TPB + threadIdx.x;
    unsigned e = g_list[i];
    if (e == SENTINEL) return;

    if (g_cnt[e] == 0u) return;             // cheap pre-gate for duplicates
    unsigned c = atomicExch(&g_cnt[e], 0u); // claim (exactly one winner)
    if (c == 0u) return;

    unsigned mk = g_maxk[e];
    unsigned nk = g_mink[e];
    float    s  = g_sum[e];
    g_maxk[e] = 0u;                         // self-clean for next call
    g_mink[e] = 0u;
    g_sum[e]  = 0.0f;

    size_t o = (size_t)e * 3;
    out[o + 0] = funkey(mk);
    out[o + 1] = funkey(~nk);
    out[o + 2] = __fdiv_rn(s, (float)c);    // cnt >= 1 here (== max(cnt,1))
}

extern "C" void kernel_launch(void* const* d_in, const int* in_sizes, int n_in,
                              void* d_out, int out_size)
{
    const float4* cr   = (const float4*)d_in[0];  // coordinates_radii (B,N,4)
    const float*  feat = (const float*)d_in[1];   // features (B,N,3)
    float*        out  = (float*)d_out;           // (B,128,128,128,3) f32

    k_zero_scatter<<<ZERO_BLOCKS + SCAT_BLOCKS, TPB>>>(cr, feat, (float4*)out);
    k_finalize<<<FIN_BLOCKS, TPB>>>(out);
}

// round 4
// speedup vs baseline: 2.8472x; 2.0092x over previous
#include <cuda_runtime.h>
#include <stdint.h>

// ---------------------------------------------------------------------------
// VanDerWallsSurface: scatter point features into a 128^3 voxel grid.
//  out[b,x,y,z] = [max f0, min f1, mean f2] over points whose sphere covers
//  the voxel (within the 5x5x5 neighborhood of round(coords)), else zeros.
//
// R4: scratch-locality redesign.
//  R3 evidence: four separate 33.5MB scratch arrays (134MB > L2) meant every
//  hit touched 4 cold 128B lines at 4B granularity (~200MB DRAM RMW in A,
//  re-missed in B; B issue=0.8% = scattered-miss latency).
//  R4: one interleaved 16B accumulator per voxel {maxk, mink, cnt, sum} ->
//  one line = all fields of 8 z-adjacent voxels; touched working set ~50MB
//  fits L2. Also drop the 16MB list round-trip: finalize recomputes candidate
//  voxels from cr (256KB) and claims each voxel once via atomicExch(cnt).
//
//  - Order-preserving uint encodings make 0 the neutral element for all four
//    accumulators -> scratch is a zero-initialized static and is re-zeroed
//    lazily (touched entries only) by the finalize kernel, keeping the
//    all-zero invariant across graph replays.
//  - Kernel A fuses the mandatory 100MB output zeroing with the atomic
//    scatter; the two halves of the grid touch disjoint memory.
// ---------------------------------------------------------------------------

#define VOL        128
#define NB         4
#define NPTS       4096
#define NPOINTS    (NB * NPTS)            // 16384
#define KOFF       125                    // 5x5x5 offsets
#define NCAND      (NPOINTS * KOFF)       // 2,048,000 candidates
#define TOTAL_VOX  (NB * VOL * VOL * VOL) // 8,388,608
#define TPB        256

#define ZPT         4                                   // float4 stores per thread
#define ZERO_VEC    ((TOTAL_VOX * 3) / 4)               // 6,291,456 float4 stores
#define ZERO_BLOCKS (ZERO_VEC / (TPB * ZPT))            // 6,144
#define SCAT_BLOCKS (NCAND / TPB)                       // 8,000
#define FIN_BLOCKS  (NCAND / TPB)                       // 8,000

// Interleaved per-voxel accumulator: one 128B cache line covers all four
// fields of 8 z-adjacent voxels. All neutral elements are 0.
struct Acc {
    unsigned int maxk;  // max-key of f0
    unsigned int mink;  // ~min-key of f1 (min via max)
    unsigned int cnt;   // hit count (also the claim token in finalize)
    float        sum;   // sum of f2
};
__device__ Acc g_acc[TOTAL_VOX];   // zero-initialized; kept zero by k_finalize

// Order-preserving float -> uint key. For any finite non-NaN f, fkey(f) > 0,
// so 0 is a valid "empty" sentinel for atomicMax accumulation.
__device__ __forceinline__ unsigned int fkey(float f) {
    unsigned int u = __float_as_uint(f);
    return (u & 0x80000000u) ? ~u : (u | 0x80000000u);
}
__device__ __forceinline__ float funkey(unsigned int k) {
    unsigned int u = (k & 0x80000000u) ? (k ^ 0x80000000u) : ~k;
    return __uint_as_float(u);
}

// Shared candidate math for kernels A and B (must be bit-identical in both).
// Returns true if candidate t (= pn*KOFF + k) hits; sets e to the voxel id.
__device__ __forceinline__ bool candidate_voxel(
    const float4* __restrict__ cr, int t, int* pn_out, unsigned* e_out)
{
    int k  = t % KOFF;
    int pn = t / KOFF;
    *pn_out = pn;

    float4 c = __ldg(cr + pn);  // 125 consecutive threads share -> L1 broadcast

    int ox = k / 25 - 2;
    int oy = (k / 5) % 5 - 2;
    int oz = k % 5 - 2;

    // jnp.round == round-half-to-even == rn conversions/rintf
    int vx = __float2int_rn(c.x) + ox;
    int vy = __float2int_rn(c.y) + oy;
    int vz = __float2int_rn(c.z) + oz;

    // Exact IEEE ops, left-to-right sum, matching the reference (no FMA
    // contraction that could flip sphere-boundary membership).
    float dx = __fsub_rn((float)vx, c.x);
    float dy = __fsub_rn((float)vy, c.y);
    float dz = __fsub_rn((float)vz, c.z);
    float d2 = __fadd_rn(__fadd_rn(__fmul_rn(dx, dx), __fmul_rn(dy, dy)),
                         __fmul_rn(dz, dz));

    float rr = __fdiv_rn(rintf(__fmul_rn(c.w, 1000.0f)), 1000.0f);
    float r2 = __fmul_rn(rr, rr);

    bool ok = (d2 <= r2)
            && ((unsigned)vx < VOL) && ((unsigned)vy < VOL) && ((unsigned)vz < VOL);

    *e_out = (unsigned)((pn >> 12) * (VOL * VOL * VOL)
                        + ((vx * VOL + vy) * VOL + vz));
    return ok;
}

// Kernel A: blocks [0, ZERO_BLOCKS) zero d_out (64B/thread); blocks
// [ZERO_BLOCKS, ...) run the scatter. The two halves touch disjoint memory.
__global__ void __launch_bounds__(TPB) k_zero_scatter(
    const float4* __restrict__ cr,     // (B*N) x [cx, cy, cz, r]
    const float*  __restrict__ feat,   // (B*N) x 3
    float4*       __restrict__ out4)   // d_out viewed as float4
{
    int bid = blockIdx.x;
    if (bid < ZERO_BLOCKS) {
        size_t base = ((size_t)bid * TPB + threadIdx.x) * ZPT;
        float4 z = make_float4(0.f, 0.f, 0.f, 0.f);
#pragma unroll
        for (int j = 0; j < ZPT; j++) out4[base + j] = z;
        return;
    }

    int t = (bid - ZERO_BLOCKS) * TPB + threadIdx.x;   // candidate id
    int pn; unsigned e;
    if (!candidate_voxel(cr, t, &pn, &e)) return;

    const float* fp = feat + (size_t)pn * 3;
    float f0 = __ldg(fp + 0);
    float f1 = __ldg(fp + 1);
    float f2 = __ldg(fp + 2);

    Acc* a = &g_acc[e];                 // all four atomics hit one 16B struct
    atomicMax(&a->maxk, fkey(f0));
    atomicMax(&a->mink, ~fkey(f1));     // min via max of complemented key
    atomicAdd(&a->cnt, 1u);
    atomicAdd(&a->sum, f2);
}

// Kernel B: recompute candidates from cr (256KB, L1-broadcast); for each hit,
// claim the voxel once (atomicExch on cnt), finalize its 3 output channels,
// and restore its scratch line to zero for the next call.
__global__ void __launch_bounds__(TPB) k_finalize(
    const float4* __restrict__ cr,
    float*        __restrict__ out)
{
    int t = blockIdx.x * TPB + threadIdx.x;
    int pn; unsigned e;
    if (!candidate_voxel(cr, t, &pn, &e)) return;

    Acc* a = &g_acc[e];
    if (a->cnt == 0u) return;               // cheap pre-gate for duplicates
    unsigned c = atomicExch(&a->cnt, 0u);   // claim (exactly one winner)
    if (c == 0u) return;

    unsigned mk = a->maxk;
    unsigned nk = a->mink;
    float    s  = a->sum;
    a->maxk = 0u;                           // self-clean for next call
    a->mink = 0u;
    a->sum  = 0.0f;

    size_t o = (size_t)e * 3;
    out[o + 0] = funkey(mk);
    out[o + 1] = funkey(~nk);
    out[o + 2] = __fdiv_rn(s, (float)c);    // cnt >= 1 here (== max(cnt,1))
}

extern "C" void kernel_launch(void* const* d_in, const int* in_sizes, int n_in,
                              void* d_out, int out_size)
{
    const float4* cr   = (const float4*)d_in[0];  // coordinates_radii (B,N,4)
    const float*  feat = (const float*)d_in[1];   // features (B,N,3)
    float*        out  = (float*)d_out;           // (B,128,128,128,3) f32

    k_zero_scatter<<<ZERO_BLOCKS + SCAT_BLOCKS, TPB>>>(cr, feat, (float4*)out);
    k_finalize<<<FIN_BLOCKS, TPB>>>(cr, out);
}

// round 5
// speedup vs baseline: 5.9897x; 2.1037x over previous
#include <cuda_runtime.h>
#include <stdint.h>

// ---------------------------------------------------------------------------
// VanDerWallsSurface: scatter point features into a 128^3 voxel grid.
//  out[b,x,y,z] = [max f0, min f1, mean f2] over points whose sphere covers
//  the voxel (within the 5x5x5 neighborhood of round(coords)), else zeros.
//
// R5: fuse finalize + output-zeroing into ONE coalesced streaming sweep.
//  R4 evidence: finalize was latency-bound (issue=7.5%) on recomputed
//  candidates + dependent scattered reads + claim atomics, and the zero pass
//  wrote 100MB that finalize partially overwrote.
//  R5: kernel A = scatter only (atomics into the interleaved 16B Acc).
//      kernel B = sequential sweep over all voxels: read Acc (uint4,
//      coalesced), write the 3 output floats (zeros or decoded), zero Acc if
//      dirty. No atomics, no duplicates, no scattered access. ~266MB of pure
//      streaming traffic -> BW-bound.
//
//  - Order-preserving uint encodings make 0 the neutral element for all four
//    accumulators -> scratch is a zero-initialized static; the sweep re-zeroes
//    dirty entries, keeping the all-zero invariant across graph replays.
// ---------------------------------------------------------------------------

#define VOL        128
#define NB         4
#define NPTS       4096
#define NPOINTS    (NB * NPTS)            // 16384
#define KOFF       125                    // 5x5x5 offsets
#define NCAND      (NPOINTS * KOFF)       // 2,048,000 candidates
#define TOTAL_VOX  (NB * VOL * VOL * VOL) // 8,388,608
#define TPB        256

#define SCAT_BLOCKS  (NCAND / TPB)        // 8,000
#define SWEEP_BLOCKS (TOTAL_VOX / TPB)    // 32,768

// Interleaved per-voxel accumulator: one 128B cache line covers all four
// fields of 8 z-adjacent voxels. All neutral elements are 0.
struct Acc {
    unsigned int maxk;  // max-key of f0
    unsigned int mink;  // ~min-key of f1 (min via max)
    unsigned int cnt;   // hit count
    float        sum;   // sum of f2
};
__device__ Acc g_acc[TOTAL_VOX];   // zero-initialized; kept zero by k_sweep

// Order-preserving float -> uint key. For any finite non-NaN f, fkey(f) > 0,
// so 0 is a valid "empty" sentinel for atomicMax accumulation.
__device__ __forceinline__ unsigned int fkey(float f) {
    unsigned int u = __float_as_uint(f);
    return (u & 0x80000000u) ? ~u : (u | 0x80000000u);
}
__device__ __forceinline__ float funkey(unsigned int k) {
    unsigned int u = (k & 0x80000000u) ? (k ^ 0x80000000u) : ~k;
    return __uint_as_float(u);
}

// Kernel A: one thread per (point, offset) candidate; hits do 4 atomics into
// the voxel's interleaved Acc (single 16B struct -> single cache line).
__global__ void __launch_bounds__(TPB) k_scatter(
    const float4* __restrict__ cr,     // (B*N) x [cx, cy, cz, r]
    const float*  __restrict__ feat)   // (B*N) x 3
{
    int t  = blockIdx.x * TPB + threadIdx.x;   // candidate id
    int k  = t % KOFF;
    int pn = t / KOFF;                         // linear point id

    float4 c = __ldg(cr + pn);  // 125 consecutive threads share -> L1 broadcast

    int ox = k / 25 - 2;
    int oy = (k / 5) % 5 - 2;
    int oz = k % 5 - 2;

    // jnp.round == round-half-to-even == rn conversions
    int vx = __float2int_rn(c.x) + ox;
    int vy = __float2int_rn(c.y) + oy;
    int vz = __float2int_rn(c.z) + oz;

    // Exact IEEE ops, left-to-right sum, matching the reference (no FMA
    // contraction that could flip sphere-boundary membership).
    float dx = __fsub_rn((float)vx, c.x);
    float dy = __fsub_rn((float)vy, c.y);
    float dz = __fsub_rn((float)vz, c.z);
    float d2 = __fadd_rn(__fadd_rn(__fmul_rn(dx, dx), __fmul_rn(dy, dy)),
                         __fmul_rn(dz, dz));

    float rr = __fdiv_rn(rintf(__fmul_rn(c.w, 1000.0f)), 1000.0f);
    float r2 = __fmul_rn(rr, rr);

    bool ok = (d2 <= r2)
            && ((unsigned)vx < VOL) && ((unsigned)vy < VOL) && ((unsigned)vz < VOL);
    if (!ok) return;

    unsigned e = (unsigned)((pn >> 12) * (VOL * VOL * VOL)
                            + ((vx * VOL + vy) * VOL + vz));

    const float* fp = feat + (size_t)pn * 3;
    float f0 = __ldg(fp + 0);
    float f1 = __ldg(fp + 1);
    float f2 = __ldg(fp + 2);

    Acc* a = &g_acc[e];
    atomicMax(&a->maxk, fkey(f0));
    atomicMax(&a->mink, ~fkey(f1));     // min via max of complemented key
    atomicAdd(&a->cnt, 1u);
    atomicAdd(&a->sum, f2);
}

// Kernel B: one thread per voxel, fully coalesced streaming sweep.
// Reads Acc once, writes the 3 output channels (zeros for untouched voxels),
// and re-zeroes dirty Acc entries. No atomics, no scattered access.
__global__ void __launch_bounds__(TPB) k_sweep(float* __restrict__ out)
{
    unsigned e = blockIdx.x * TPB + threadIdx.x;

    // Acc is 16B -> read as one uint4 (streaming: each line used once).
    uint4 a = __ldcs(reinterpret_cast<const uint4*>(g_acc) + e);

    float o0 = 0.0f, o1 = 0.0f, o2 = 0.0f;
    if (a.z != 0u) {                         // cnt != 0
        o0 = funkey(a.x);
        o1 = funkey(~a.y);
        o2 = __fdiv_rn(__uint_as_float(a.w), (float)a.z);  // sum / cnt
        __stcs(reinterpret_cast<uint4*>(g_acc) + e,
               make_uint4(0u, 0u, 0u, 0u));  // self-clean for next call
    }

    size_t o = (size_t)e * 3;                // 12B/thread, coalesced per warp
    __stcs(out + o + 0, o0);
    __stcs(out + o + 1, o1);
    __stcs(out + o + 2, o2);
}

extern "C" void kernel_launch(void* const* d_in, const int* in_sizes, int n_in,
                              void* d_out, int out_size)
{
    const float4* cr   = (const float4*)d_in[0];  // coordinates_radii (B,N,4)
    const float*  feat = (const float*)d_in[1];   // features (B,N,3)
    float*        out  = (float*)d_out;           // (B,128,128,128,3) f32

    k_scatter<<<SCAT_BLOCKS, TPB>>>(cr, feat);
    k_sweep<<<SWEEP_BLOCKS, TPB>>>(out);
}